// round 9
// baseline (speedup 1.0000x reference)
#include <cuda_runtime.h>
#include <cuda_fp16.h>
#include <stdint.h>

#define MAX_NODES 50000
#define MAX_EDGES 800000
#define FD        128
#define NRELS     4
#define NTILES    13

// Scratch (fp16): hW[r][n][128], hF[r][n][256] (gamma | beta)
__device__ __half g_hW[NRELS * MAX_NODES * 128];   // 51.2 MB
__device__ __half g_hF[NRELS * MAX_NODES * 256];   // 102.4 MB
// Pre-swizzled fp16 weight tiles: 32KB per tile
__device__ unsigned char g_Bw[NTILES * 32768];     // 416 KB (L2-resident)
// Edge sort by key = dst*4 + etype
__device__ int      g_cnt[NRELS * MAX_NODES];      // per-bin counts
__device__ int      g_off[NRELS * MAX_NODES + 1];  // prefix offsets
__device__ int      g_pos[NRELS * MAX_NODES];      // scatter cursors
__device__ uint32_t g_srt[MAX_EDGES];              // src ids sorted by key

// ---------------------------------------------------------------------------
// Swizzle map for 128x128 fp16 tile [row][k]: row stride 256B, 16B chunks
// XOR-permuted by row&7 -> conflict-free ldmatrix.
// ---------------------------------------------------------------------------
__host__ __device__ __forceinline__ uint32_t amap(int row, int k2) {
    return (uint32_t)(row * 256 + ((((k2 >> 4) ^ (row & 7)) << 4) | (k2 & 15)));
}

__device__ __forceinline__ uint32_t smem_u32(const void* p) {
    uint32_t a;
    asm("{ .reg .u64 t; cvta.to.shared.u64 t, %1; cvt.u32.u64 %0, t; }"
        : "=r"(a) : "l"(p));
    return a;
}

__device__ __forceinline__ void ldsm_x4(uint32_t* r, uint32_t addr) {
    asm volatile("ldmatrix.sync.aligned.m8n8.x4.shared.b16 {%0,%1,%2,%3}, [%4];"
                 : "=r"(r[0]), "=r"(r[1]), "=r"(r[2]), "=r"(r[3]) : "r"(addr));
}
__device__ __forceinline__ void ldsm_x2(uint32_t* r, uint32_t addr) {
    asm volatile("ldmatrix.sync.aligned.m8n8.x2.shared.b16 {%0,%1}, [%2];"
                 : "=r"(r[0]), "=r"(r[1]) : "r"(addr));
}
__device__ __forceinline__ void mma16816(float* c, const uint32_t* a, const uint32_t* b) {
    asm volatile("mma.sync.aligned.m16n8k16.row.col.f32.f16.f16.f32 "
                 "{%0,%1,%2,%3}, {%4,%5,%6,%7}, {%8,%9}, {%0,%1,%2,%3};"
                 : "+f"(c[0]), "+f"(c[1]), "+f"(c[2]), "+f"(c[3])
                 : "r"(a[0]), "r"(a[1]), "r"(a[2]), "r"(a[3]), "r"(b[0]), "r"(b[1]));
}
#define CP_ASYNC16(dst, src) \
    asm volatile("cp.async.ca.shared.global [%0], [%1], 16;" :: "r"(dst), "l"(src) : "memory")
#define CP_COMMIT() asm volatile("cp.async.commit_group;" ::: "memory")
#define CP_WAIT(n)  asm volatile("cp.async.wait_group %0;" :: "n"(n) : "memory")

__device__ __forceinline__ uint32_t cvt2h(float v0, float v1) {
    __half h0 = __float2half_rn(v0);
    __half h1 = __float2half_rn(v1);
    return (uint32_t)__half_as_ushort(h0) | ((uint32_t)__half_as_ushort(h1) << 16);
}

// ---------------------------------------------------------------------------
// Prep: weights -> fp16, transposed to [n][k], pre-swizzled. 104 blocks.
// ---------------------------------------------------------------------------
__global__ __launch_bounds__(256)
void prep_weights(const float* __restrict__ W_rel,
                  const float* __restrict__ film_rel,
                  const float* __restrict__ loop_w)
{
    const int ct   = blockIdx.x >> 3;
    const int part = blockIdx.x & 7;
    const int tid  = threadIdx.x;

    const float* bptr;
    int strideD;
    if (ct < 4)       { bptr = W_rel + (size_t)ct * FD * 128; strideD = 128; }
    else if (ct < 12) {
        int idx = ct - 4, rel = idx >> 1, half = idx & 1;
        bptr = film_rel + (size_t)rel * FD * 256 + half * 128;
        strideD = 256;
    }
    else              { bptr = loop_w; strideD = 128; }

    unsigned char* dhi = g_Bw + (size_t)ct * 32768;

    #pragma unroll
    for (int s = 0; s < 2; ++s) {
        int li = (part * 2 + s) * 256 + tid;
        int n  = li & 127;
        int d4 = (li >> 7) * 4;
        uint32_t w0 = cvt2h(__ldg(bptr + (size_t)(d4    ) * strideD + n),
                            __ldg(bptr + (size_t)(d4 + 1) * strideD + n));
        uint32_t w1 = cvt2h(__ldg(bptr + (size_t)(d4 + 2) * strideD + n),
                            __ldg(bptr + (size_t)(d4 + 3) * strideD + n));
        *reinterpret_cast<uint2*>(dhi + amap(n, d4 * 2)) = make_uint2(w0, w1);
    }
}

// ---------------------------------------------------------------------------
// GEMM via mma.sync fp16 single-pass: D = A * B (fp32 accum)
// SMEM: A (32K) | B double buffer (2 x 32K) = 96K -> 2 CTAs/SM
// ---------------------------------------------------------------------------
#define SO_A  0
#define SO_B  32768
#define SMEM_TOT (32768 + 2 * 32768)

__global__ __launch_bounds__(256, 2)
void gemm_mma_kernel(const float* __restrict__ feat,
                     const float* __restrict__ h_bias,
                     float* __restrict__ out,
                     int Nn)
{
    extern __shared__ unsigned char smem[];
    const uint32_t sb = smem_u32(smem);
    const int tid  = threadIdx.x;
    const int wid  = tid >> 5;
    const int lane = tid & 31;
    const int m_base = blockIdx.x * 128;

    // ---- Convert A tile to fp16 SMEM, swizzled ----
    #pragma unroll
    for (int it = 0; it < 16; ++it) {
        int li = it * 256 + tid;
        int m  = li >> 5;
        int k4 = (li & 31) * 4;
        float4 v = make_float4(0.f, 0.f, 0.f, 0.f);
        int row = m_base + m;
        if (row < Nn)
            v = *reinterpret_cast<const float4*>(feat + (size_t)row * FD + k4);
        *reinterpret_cast<uint2*>(smem + SO_A + amap(m, k4 * 2)) =
            make_uint2(cvt2h(v.x, v.y), cvt2h(v.z, v.w));
    }

    const int wm = (wid & 1) * 64;
    const int wn = (wid >> 1) * 32;
    const int lrow_a = lane & 15;
    const int lkh_a  = lane >> 4;
    const int lrow_b = lane & 7;
    const int lkh_b  = (lane >> 3) & 1;
    const int xr7    = lane & 7;

    uint32_t rowoffA[4], rowoffB[4];
    #pragma unroll
    for (int mt = 0; mt < 4; ++mt) rowoffA[mt] = (uint32_t)((wm + mt * 16 + lrow_a) * 256);
    #pragma unroll
    for (int nt = 0; nt < 4; ++nt) rowoffB[nt] = (uint32_t)((wn + nt * 8 + lrow_b) * 256);

    const uint32_t sA = sb + SO_A;

    {   // prefetch B tile 0
        const unsigned char* src = g_Bw;
        uint32_t dst = sb + SO_B;
        #pragma unroll
        for (int i = 0; i < 8; ++i) {
            int idx = i * 256 + tid;
            CP_ASYNC16(dst + idx * 16, src + (size_t)idx * 16);
        }
        CP_COMMIT();
    }

    for (int ct = 0; ct < NTILES; ++ct) {
        if (ct + 1 < NTILES) {
            const unsigned char* src = g_Bw + (size_t)(ct + 1) * 32768;
            uint32_t dst = sb + SO_B + ((ct + 1) & 1) * 32768;
            #pragma unroll
            for (int i = 0; i < 8; ++i) {
                int idx = i * 256 + tid;
                CP_ASYNC16(dst + idx * 16, src + (size_t)idx * 16);
            }
            CP_COMMIT();
            CP_WAIT(1);
        } else {
            CP_WAIT(0);
        }
        __syncthreads();

        const uint32_t sB = sb + SO_B + (ct & 1) * 32768;

        float acc[4][4][4];
        #pragma unroll
        for (int mt = 0; mt < 4; ++mt)
            #pragma unroll
            for (int nt = 0; nt < 4; ++nt)
                #pragma unroll
                for (int q = 0; q < 4; ++q) acc[mt][nt][q] = 0.f;

        #pragma unroll
        for (int ks = 0; ks < 8; ++ks) {
            uint32_t cA = (uint32_t)((((2 * ks + lkh_a) ^ xr7) & 15) << 4);
            uint32_t cB = (uint32_t)((((2 * ks + lkh_b) ^ xr7) & 15) << 4);
            uint32_t a[4][4];
            #pragma unroll
            for (int mt = 0; mt < 4; ++mt) ldsm_x4(a[mt], sA + rowoffA[mt] + cA);
            uint32_t bh[4][2];
            #pragma unroll
            for (int nt = 0; nt < 4; ++nt) ldsm_x2(bh[nt], sB + rowoffB[nt] + cB);
            #pragma unroll
            for (int mt = 0; mt < 4; ++mt)
                #pragma unroll
                for (int nt = 0; nt < 4; ++nt)
                    mma16816(acc[mt][nt], a[mt], bh[nt]);
        }

        // ---- Epilogue ----
        if (ct == 12) {
            float2 bias2[4];
            #pragma unroll
            for (int nt = 0; nt < 4; ++nt)
                bias2[nt] = *reinterpret_cast<const float2*>(
                    h_bias + wn + nt * 8 + (lane & 3) * 2);
            #pragma unroll
            for (int mt = 0; mt < 4; ++mt) {
                int r0 = m_base + wm + mt * 16 + (lane >> 2);
                #pragma unroll
                for (int nt = 0; nt < 4; ++nt) {
                    int col = wn + nt * 8 + (lane & 3) * 2;
                    float2 v0 = make_float2(acc[mt][nt][0] + bias2[nt].x,
                                            acc[mt][nt][1] + bias2[nt].y);
                    float2 v1 = make_float2(acc[mt][nt][2] + bias2[nt].x,
                                            acc[mt][nt][3] + bias2[nt].y);
                    if (r0 < Nn)
                        *reinterpret_cast<float2*>(out + (size_t)r0 * 128 + col) = v0;
                    if (r0 + 8 < Nn)
                        *reinterpret_cast<float2*>(out + (size_t)(r0 + 8) * 128 + col) = v1;
                }
            }
        } else {
            __half* obase;
            int so;
            if (ct < 4) { obase = g_hW + (size_t)ct * Nn * 128; so = 128; }
            else {
                int idx = ct - 4, rel = idx >> 1, half = idx & 1;
                obase = g_hF + (size_t)rel * Nn * 256 + half * 128;
                so = 256;
            }
            #pragma unroll
            for (int mt = 0; mt < 4; ++mt) {
                int r0 = m_base + wm + mt * 16 + (lane >> 2);
                #pragma unroll
                for (int nt = 0; nt < 4; ++nt) {
                    int col = wn + nt * 8 + (lane & 3) * 2;
                    if (r0 < Nn)
                        *reinterpret_cast<uint32_t*>(obase + (size_t)r0 * so + col) =
                            cvt2h(acc[mt][nt][0], acc[mt][nt][1]);
                    if (r0 + 8 < Nn)
                        *reinterpret_cast<uint32_t*>(obase + (size_t)(r0 + 8) * so + col) =
                            cvt2h(acc[mt][nt][2], acc[mt][nt][3]);
                }
            }
        }
        __syncthreads();
    }
}

// ---------------------------------------------------------------------------
// Edge sort: key = dst*4 + etype
// ---------------------------------------------------------------------------
__global__ void zero_cnt(int nbins) {
    int i = blockIdx.x * blockDim.x + threadIdx.x;
    if (i < nbins) g_cnt[i] = 0;
}

__global__ void hist_kernel(const int* __restrict__ dst, const int* __restrict__ et, int E) {
    int i = blockIdx.x * blockDim.x + threadIdx.x;
    if (i < E) atomicAdd(&g_cnt[dst[i] * NRELS + et[i]], 1);
}

__global__ __launch_bounds__(1024)
void scan_kernel(int nbins, int E) {
    __shared__ int sh[1024];
    const int t = threadIdx.x;
    const int chunk = (nbins + 1023) / 1024;
    const int lo = t * chunk;
    const int hi = min(lo + chunk, nbins);

    int local = 0;
    for (int i = lo; i < hi; ++i) local += g_cnt[i];
    sh[t] = local;
    __syncthreads();
    // Hillis-Steele inclusive scan
    for (int off = 1; off < 1024; off <<= 1) {
        int v = (t >= off) ? sh[t - off] : 0;
        __syncthreads();
        sh[t] += v;
        __syncthreads();
    }
    int run = sh[t] - local;   // exclusive prefix
    for (int i = lo; i < hi; ++i) {
        int c = g_cnt[i];
        g_off[i] = run;
        g_pos[i] = run;
        run += c;
    }
    if (t == 1023) g_off[nbins] = E;
}

__global__ void scatter_kernel(const int* __restrict__ src, const int* __restrict__ dst,
                               const int* __restrict__ et, int E) {
    int i = blockIdx.x * blockDim.x + threadIdx.x;
    if (i < E) {
        int idx = atomicAdd(&g_pos[dst[i] * NRELS + et[i]], 1);
        g_srt[idx] = (uint32_t)src[i];
    }
}

// ---------------------------------------------------------------------------
// Segmented edge kernel: one warp per dst node, atomic-free.
//   For each non-empty rel segment: load gamma/beta once, sum relu(g*m+b)
//   over the segment's src rows, then RMW the out row once.
// ---------------------------------------------------------------------------
__global__ __launch_bounds__(256)
void edge_seg_kernel(float* __restrict__ out, int N)
{
    int d = (blockIdx.x * blockDim.x + threadIdx.x) >> 5;
    if (d >= N) return;
    int lane = threadIdx.x & 31;

    int seg0 = g_off[d * NRELS];
    int seg4 = g_off[d * NRELS + NRELS];
    if (seg0 == seg4) return;   // isolated node: out already has loop+bias

    float acc0 = 0.f, acc1 = 0.f, acc2 = 0.f, acc3 = 0.f;

    #pragma unroll
    for (int rel = 0; rel < NRELS; ++rel) {
        int b = g_off[d * NRELS + rel];
        int e = g_off[d * NRELS + rel + 1];
        if (b == e) continue;

        const uint2* fRow = reinterpret_cast<const uint2*>(
            g_hF + ((size_t)rel * N + d) * 256);
        uint2 gu = __ldg(fRow + lane);        // gamma (4 halves)
        uint2 bu = __ldg(fRow + lane + 32);   // beta
        float2 gA = __half22float2(*reinterpret_cast<const __half2*>(&gu.x));
        float2 gB = __half22float2(*reinterpret_cast<const __half2*>(&gu.y));
        float2 bA = __half22float2(*reinterpret_cast<const __half2*>(&bu.x));
        float2 bB = __half22float2(*reinterpret_cast<const __half2*>(&bu.y));

        const __half* hWr = g_hW + (size_t)rel * N * 128;
        for (int i = b; i < e; ++i) {
            int s = (int)__ldg(&g_srt[i]);
            uint2 mu = __ldg(reinterpret_cast<const uint2*>(hWr + (size_t)s * 128) + lane);
            float2 mA = __half22float2(*reinterpret_cast<const __half2*>(&mu.x));
            float2 mB = __half22float2(*reinterpret_cast<const __half2*>(&mu.y));
            acc0 += fmaxf(fmaf(gA.x, mA.x, bA.x), 0.f);
            acc1 += fmaxf(fmaf(gA.y, mA.y, bA.y), 0.f);
            acc2 += fmaxf(fmaf(gB.x, mB.x, bB.x), 0.f);
            acc3 += fmaxf(fmaf(gB.y, mB.y, bB.y), 0.f);
        }
    }

    float4* o = reinterpret_cast<float4*>(out + (size_t)d * 128) + lane;
    float4 cur = *o;
    cur.x += acc0; cur.y += acc1; cur.z += acc2; cur.w += acc3;
    *o = cur;
}

// ---------------------------------------------------------------------------
extern "C" void kernel_launch(void* const* d_in, const int* in_sizes, int n_in,
                              void* d_out, int out_size)
{
    const float* feat   = (const float*)d_in[0];
    const int*   src    = (const int*)  d_in[1];
    const int*   dst    = (const int*)  d_in[2];
    const int*   etypes = (const int*)  d_in[3];
    const float* W_rel  = (const float*)d_in[4];
    const float* film   = (const float*)d_in[5];
    const float* bias   = (const float*)d_in[6];
    const float* loopw  = (const float*)d_in[7];
    float* out = (float*)d_out;

    const int N = in_sizes[0] / FD;     // 50000
    const int E = in_sizes[1];          // 800000
    const int nbins = N * NRELS;

    cudaFuncSetAttribute(gemm_mma_kernel,
                         cudaFuncAttributeMaxDynamicSharedMemorySize, SMEM_TOT);

    // Edge sort (independent of GEMM)
    zero_cnt<<<(nbins + 1023) / 1024, 1024>>>(nbins);
    hist_kernel<<<(E + 255) / 256, 256>>>(dst, etypes, E);
    scan_kernel<<<1, 1024>>>(nbins, E);
    scatter_kernel<<<(E + 255) / 256, 256>>>(src, dst, etypes, E);

    // Dense phase
    prep_weights<<<NTILES * 8, 256>>>(W_rel, film, loopw);
    int mtiles = (N + 127) / 128;
    gemm_mma_kernel<<<mtiles, 256, SMEM_TOT>>>(feat, bias, out, N);

    // Segmented aggregation (needs hW/hF/out + sort)
    edge_seg_kernel<<<(N * 32 + 255) / 256, 256>>>(out, N);
}

// round 11
// speedup vs baseline: 2.3644x; 2.3644x over previous
#include <cuda_runtime.h>
#include <cuda_fp16.h>
#include <stdint.h>

#define MAX_NODES 50000
#define MAX_EDGES 800000
#define FD        128
#define NRELS     4
#define NTILES    13
#define NBINS_MAX (NRELS * MAX_NODES)
#define SCAN_BLK  1024
#define NBLK1     ((NBINS_MAX + SCAN_BLK - 1) / SCAN_BLK)   // 196

// Scratch (fp16): hW[r][n][128], hF[r][n][256] (gamma | beta)
__device__ __half g_hW[NRELS * MAX_NODES * 128];   // 51.2 MB
__device__ __half g_hF[NRELS * MAX_NODES * 256];   // 102.4 MB
// Pre-swizzled fp16 weight tiles: 32KB per tile
__device__ unsigned char g_Bw[NTILES * 32768];     // 416 KB (L2-resident)
// Edge sort by key = dst*4 + etype
__device__ int      g_cnt[NBINS_MAX];
__device__ int      g_off[NBINS_MAX + 1];
__device__ int      g_pos[NBINS_MAX];
__device__ int      g_blksum[256];
__device__ int      g_blkpre[256];
__device__ uint32_t g_srt[MAX_EDGES];

// ---------------------------------------------------------------------------
// Swizzle map for 128x128 fp16 tile [row][k]: row stride 256B, 16B chunks
// XOR-permuted by row&7 -> conflict-free ldmatrix.
// ---------------------------------------------------------------------------
__host__ __device__ __forceinline__ uint32_t amap(int row, int k2) {
    return (uint32_t)(row * 256 + ((((k2 >> 4) ^ (row & 7)) << 4) | (k2 & 15)));
}

__device__ __forceinline__ uint32_t smem_u32(const void* p) {
    uint32_t a;
    asm("{ .reg .u64 t; cvta.to.shared.u64 t, %1; cvt.u32.u64 %0, t; }"
        : "=r"(a) : "l"(p));
    return a;
}

__device__ __forceinline__ void ldsm_x4(uint32_t* r, uint32_t addr) {
    asm volatile("ldmatrix.sync.aligned.m8n8.x4.shared.b16 {%0,%1,%2,%3}, [%4];"
                 : "=r"(r[0]), "=r"(r[1]), "=r"(r[2]), "=r"(r[3]) : "r"(addr));
}
__device__ __forceinline__ void ldsm_x2(uint32_t* r, uint32_t addr) {
    asm volatile("ldmatrix.sync.aligned.m8n8.x2.shared.b16 {%0,%1}, [%2];"
                 : "=r"(r[0]), "=r"(r[1]) : "r"(addr));
}
__device__ __forceinline__ void mma16816(float* c, const uint32_t* a, const uint32_t* b) {
    asm volatile("mma.sync.aligned.m16n8k16.row.col.f32.f16.f16.f32 "
                 "{%0,%1,%2,%3}, {%4,%5,%6,%7}, {%8,%9}, {%0,%1,%2,%3};"
                 : "+f"(c[0]), "+f"(c[1]), "+f"(c[2]), "+f"(c[3])
                 : "r"(a[0]), "r"(a[1]), "r"(a[2]), "r"(a[3]), "r"(b[0]), "r"(b[1]));
}
#define CP_ASYNC16(dst, src) \
    asm volatile("cp.async.ca.shared.global [%0], [%1], 16;" :: "r"(dst), "l"(src) : "memory")
#define CP_COMMIT() asm volatile("cp.async.commit_group;" ::: "memory")
#define CP_WAIT(n)  asm volatile("cp.async.wait_group %0;" :: "n"(n) : "memory")

__device__ __forceinline__ uint32_t cvt2h(float v0, float v1) {
    __half h0 = __float2half_rn(v0);
    __half h1 = __float2half_rn(v1);
    return (uint32_t)__half_as_ushort(h0) | ((uint32_t)__half_as_ushort(h1) << 16);
}

// ---------------------------------------------------------------------------
// Prep: weights -> fp16, transposed to [n][k], pre-swizzled. 104 blocks.
// ---------------------------------------------------------------------------
__global__ __launch_bounds__(256)
void prep_weights(const float* __restrict__ W_rel,
                  const float* __restrict__ film_rel,
                  const float* __restrict__ loop_w)
{
    const int ct   = blockIdx.x >> 3;
    const int part = blockIdx.x & 7;
    const int tid  = threadIdx.x;

    const float* bptr;
    int strideD;
    if (ct < 4)       { bptr = W_rel + (size_t)ct * FD * 128; strideD = 128; }
    else if (ct < 12) {
        int idx = ct - 4, rel = idx >> 1, half = idx & 1;
        bptr = film_rel + (size_t)rel * FD * 256 + half * 128;
        strideD = 256;
    }
    else              { bptr = loop_w; strideD = 128; }

    unsigned char* dhi = g_Bw + (size_t)ct * 32768;

    #pragma unroll
    for (int s = 0; s < 2; ++s) {
        int li = (part * 2 + s) * 256 + tid;
        int n  = li & 127;
        int d4 = (li >> 7) * 4;
        uint32_t w0 = cvt2h(__ldg(bptr + (size_t)(d4    ) * strideD + n),
                            __ldg(bptr + (size_t)(d4 + 1) * strideD + n));
        uint32_t w1 = cvt2h(__ldg(bptr + (size_t)(d4 + 2) * strideD + n),
                            __ldg(bptr + (size_t)(d4 + 3) * strideD + n));
        *reinterpret_cast<uint2*>(dhi + amap(n, d4 * 2)) = make_uint2(w0, w1);
    }
}

// ---------------------------------------------------------------------------
// GEMM via mma.sync fp16 single-pass: D = A * B (fp32 accum)
// SMEM: A (32K) | B double buffer (2 x 32K) = 96K -> 2 CTAs/SM
// ---------------------------------------------------------------------------
#define SO_A  0
#define SO_B  32768
#define SMEM_TOT (32768 + 2 * 32768)

__global__ __launch_bounds__(256, 2)
void gemm_mma_kernel(const float* __restrict__ feat,
                     const float* __restrict__ h_bias,
                     float* __restrict__ out,
                     int Nn)
{
    extern __shared__ unsigned char smem[];
    const uint32_t sb = smem_u32(smem);
    const int tid  = threadIdx.x;
    const int wid  = tid >> 5;
    const int lane = tid & 31;
    const int m_base = blockIdx.x * 128;

    // ---- Convert A tile to fp16 SMEM, swizzled ----
    #pragma unroll
    for (int it = 0; it < 16; ++it) {
        int li = it * 256 + tid;
        int m  = li >> 5;
        int k4 = (li & 31) * 4;
        float4 v = make_float4(0.f, 0.f, 0.f, 0.f);
        int row = m_base + m;
        if (row < Nn)
            v = *reinterpret_cast<const float4*>(feat + (size_t)row * FD + k4);
        *reinterpret_cast<uint2*>(smem + SO_A + amap(m, k4 * 2)) =
            make_uint2(cvt2h(v.x, v.y), cvt2h(v.z, v.w));
    }

    const int wm = (wid & 1) * 64;
    const int wn = (wid >> 1) * 32;
    const int lrow_a = lane & 15;
    const int lkh_a  = lane >> 4;
    const int lrow_b = lane & 7;
    const int lkh_b  = (lane >> 3) & 1;
    const int xr7    = lane & 7;

    uint32_t rowoffA[4], rowoffB[4];
    #pragma unroll
    for (int mt = 0; mt < 4; ++mt) rowoffA[mt] = (uint32_t)((wm + mt * 16 + lrow_a) * 256);
    #pragma unroll
    for (int nt = 0; nt < 4; ++nt) rowoffB[nt] = (uint32_t)((wn + nt * 8 + lrow_b) * 256);

    const uint32_t sA = sb + SO_A;

    {   // prefetch B tile 0
        const unsigned char* src = g_Bw;
        uint32_t dst = sb + SO_B;
        #pragma unroll
        for (int i = 0; i < 8; ++i) {
            int idx = i * 256 + tid;
            CP_ASYNC16(dst + idx * 16, src + (size_t)idx * 16);
        }
        CP_COMMIT();
    }

    for (int ct = 0; ct < NTILES; ++ct) {
        if (ct + 1 < NTILES) {
            const unsigned char* src = g_Bw + (size_t)(ct + 1) * 32768;
            uint32_t dst = sb + SO_B + ((ct + 1) & 1) * 32768;
            #pragma unroll
            for (int i = 0; i < 8; ++i) {
                int idx = i * 256 + tid;
                CP_ASYNC16(dst + idx * 16, src + (size_t)idx * 16);
            }
            CP_COMMIT();
            CP_WAIT(1);
        } else {
            CP_WAIT(0);
        }
        __syncthreads();

        const uint32_t sB = sb + SO_B + (ct & 1) * 32768;

        float acc[4][4][4];
        #pragma unroll
        for (int mt = 0; mt < 4; ++mt)
            #pragma unroll
            for (int nt = 0; nt < 4; ++nt)
                #pragma unroll
                for (int q = 0; q < 4; ++q) acc[mt][nt][q] = 0.f;

        #pragma unroll
        for (int ks = 0; ks < 8; ++ks) {
            uint32_t cA = (uint32_t)((((2 * ks + lkh_a) ^ xr7) & 15) << 4);
            uint32_t cB = (uint32_t)((((2 * ks + lkh_b) ^ xr7) & 15) << 4);
            uint32_t a[4][4];
            #pragma unroll
            for (int mt = 0; mt < 4; ++mt) ldsm_x4(a[mt], sA + rowoffA[mt] + cA);
            uint32_t bh[4][2];
            #pragma unroll
            for (int nt = 0; nt < 4; ++nt) ldsm_x2(bh[nt], sB + rowoffB[nt] + cB);
            #pragma unroll
            for (int mt = 0; mt < 4; ++mt)
                #pragma unroll
                for (int nt = 0; nt < 4; ++nt)
                    mma16816(acc[mt][nt], a[mt], bh[nt]);
        }

        // ---- Epilogue ----
        if (ct == 12) {
            float2 bias2[4];
            #pragma unroll
            for (int nt = 0; nt < 4; ++nt)
                bias2[nt] = *reinterpret_cast<const float2*>(
                    h_bias + wn + nt * 8 + (lane & 3) * 2);
            #pragma unroll
            for (int mt = 0; mt < 4; ++mt) {
                int r0 = m_base + wm + mt * 16 + (lane >> 2);
                #pragma unroll
                for (int nt = 0; nt < 4; ++nt) {
                    int col = wn + nt * 8 + (lane & 3) * 2;
                    float2 v0 = make_float2(acc[mt][nt][0] + bias2[nt].x,
                                            acc[mt][nt][1] + bias2[nt].y);
                    float2 v1 = make_float2(acc[mt][nt][2] + bias2[nt].x,
                                            acc[mt][nt][3] + bias2[nt].y);
                    if (r0 < Nn)
                        *reinterpret_cast<float2*>(out + (size_t)r0 * 128 + col) = v0;
                    if (r0 + 8 < Nn)
                        *reinterpret_cast<float2*>(out + (size_t)(r0 + 8) * 128 + col) = v1;
                }
            }
        } else {
            __half* obase;
            int so;
            if (ct < 4) { obase = g_hW + (size_t)ct * Nn * 128; so = 128; }
            else {
                int idx = ct - 4, rel = idx >> 1, half = idx & 1;
                obase = g_hF + (size_t)rel * Nn * 256 + half * 128;
                so = 256;
            }
            #pragma unroll
            for (int mt = 0; mt < 4; ++mt) {
                int r0 = m_base + wm + mt * 16 + (lane >> 2);
                #pragma unroll
                for (int nt = 0; nt < 4; ++nt) {
                    int col = wn + nt * 8 + (lane & 3) * 2;
                    if (r0 < Nn)
                        *reinterpret_cast<uint32_t*>(obase + (size_t)r0 * so + col) =
                            cvt2h(acc[mt][nt][0], acc[mt][nt][1]);
                    if (r0 + 8 < Nn)
                        *reinterpret_cast<uint32_t*>(obase + (size_t)(r0 + 8) * so + col) =
                            cvt2h(acc[mt][nt][2], acc[mt][nt][3]);
                }
            }
        }
        __syncthreads();
    }
}

// ---------------------------------------------------------------------------
// Edge sort: key = dst*4 + etype. Coalesced 3-level scan.
// ---------------------------------------------------------------------------
__global__ void zero_cnt(int nbins) {
    int i = blockIdx.x * blockDim.x + threadIdx.x;
    if (i < nbins) g_cnt[i] = 0;
}

__global__ void hist_kernel(const int* __restrict__ dst, const int* __restrict__ et, int E) {
    int i = blockIdx.x * blockDim.x + threadIdx.x;
    if (i < E) atomicAdd(&g_cnt[dst[i] * NRELS + et[i]], 1);
}

// Level 1: per-block inclusive scan of 1024 contiguous bins (coalesced)
__global__ __launch_bounds__(SCAN_BLK)
void scan1_kernel(int nbins) {
    __shared__ int sh[SCAN_BLK];
    const int t = threadIdx.x;
    const int i = blockIdx.x * SCAN_BLK + t;
    int v = (i < nbins) ? g_cnt[i] : 0;
    sh[t] = v;
    __syncthreads();
    #pragma unroll
    for (int off = 1; off < SCAN_BLK; off <<= 1) {
        int u = (t >= off) ? sh[t - off] : 0;
        __syncthreads();
        sh[t] += u;
        __syncthreads();
    }
    if (i < nbins) g_off[i] = sh[t] - v;      // exclusive within block
    if (t == SCAN_BLK - 1) g_blksum[blockIdx.x] = sh[t];
}

// Level 2: scan the block sums (nblk <= 256), single block
__global__ __launch_bounds__(256)
void scan2_kernel(int nblk, int nbins, int E) {
    __shared__ int sh[256];
    const int t = threadIdx.x;
    int v = (t < nblk) ? g_blksum[t] : 0;
    sh[t] = v;
    __syncthreads();
    #pragma unroll
    for (int off = 1; off < 256; off <<= 1) {
        int u = (t >= off) ? sh[t - off] : 0;
        __syncthreads();
        sh[t] += u;
        __syncthreads();
    }
    if (t < nblk) g_blkpre[t] = sh[t] - v;    // exclusive block prefix
    if (t == 0) g_off[nbins] = E;
}

// Level 3: add block prefix, materialize g_off and g_pos (coalesced)
__global__ __launch_bounds__(SCAN_BLK)
void scan3_kernel(int nbins) {
    const int i = blockIdx.x * SCAN_BLK + threadIdx.x;
    if (i < nbins) {
        int o = g_off[i] + g_blkpre[blockIdx.x];
        g_off[i] = o;
        g_pos[i] = o;
    }
}

__global__ void scatter_kernel(const int* __restrict__ src, const int* __restrict__ dst,
                               const int* __restrict__ et, int E) {
    int i = blockIdx.x * blockDim.x + threadIdx.x;
    if (i < E) {
        int idx = atomicAdd(&g_pos[dst[i] * NRELS + et[i]], 1);
        g_srt[idx] = (uint32_t)src[i];
    }
}

// ---------------------------------------------------------------------------
// Segmented edge kernel: one warp per dst node, atomic-free.
// Batch src indices via coalesced lane load + shfl; 2-way unrolled gathers.
// ---------------------------------------------------------------------------
__global__ __launch_bounds__(256)
void edge_seg_kernel(float* __restrict__ out, int N)
{
    int d = (blockIdx.x * blockDim.x + threadIdx.x) >> 5;
    if (d >= N) return;
    int lane = threadIdx.x & 31;

    int seg0 = g_off[d * NRELS];
    int seg4 = g_off[d * NRELS + NRELS];
    if (seg0 == seg4) return;   // isolated node: out already has loop+bias

    float acc0 = 0.f, acc1 = 0.f, acc2 = 0.f, acc3 = 0.f;

    #pragma unroll
    for (int rel = 0; rel < NRELS; ++rel) {
        int b = g_off[d * NRELS + rel];
        int e = g_off[d * NRELS + rel + 1];
        if (b == e) continue;

        const uint2* fRow = reinterpret_cast<const uint2*>(
            g_hF + ((size_t)rel * N + d) * 256);
        uint2 gu = __ldg(fRow + lane);        // gamma (4 halves)
        uint2 bu = __ldg(fRow + lane + 32);   // beta
        float2 gA = __half22float2(*reinterpret_cast<const __half2*>(&gu.x));
        float2 gB = __half22float2(*reinterpret_cast<const __half2*>(&gu.y));
        float2 bA = __half22float2(*reinterpret_cast<const __half2*>(&bu.x));
        float2 bB = __half22float2(*reinterpret_cast<const __half2*>(&bu.y));

        const __half* hWr = g_hW + (size_t)rel * N * 128;

        for (int base = b; base < e; base += 32) {
            int cnt = min(32, e - base);
            int sidx = (lane < cnt) ? (int)__ldg(&g_srt[base + lane]) : 0;

            int j = 0;
            for (; j + 2 <= cnt; j += 2) {
                int s0 = __shfl_sync(0xffffffffu, sidx, j);
                int s1 = __shfl_sync(0xffffffffu, sidx, j + 1);
                uint2 mu0 = __ldg(reinterpret_cast<const uint2*>(hWr + (size_t)s0 * 128) + lane);
                uint2 mu1 = __ldg(reinterpret_cast<const uint2*>(hWr + (size_t)s1 * 128) + lane);
                float2 a0 = __half22float2(*reinterpret_cast<const __half2*>(&mu0.x));
                float2 a1 = __half22float2(*reinterpret_cast<const __half2*>(&mu0.y));
                acc0 += fmaxf(fmaf(gA.x, a0.x, bA.x), 0.f);
                acc1 += fmaxf(fmaf(gA.y, a0.y, bA.y), 0.f);
                acc2 += fmaxf(fmaf(gB.x, a1.x, bB.x), 0.f);
                acc3 += fmaxf(fmaf(gB.y, a1.y, bB.y), 0.f);
                float2 c0 = __half22float2(*reinterpret_cast<const __half2*>(&mu1.x));
                float2 c1 = __half22float2(*reinterpret_cast<const __half2*>(&mu1.y));
                acc0 += fmaxf(fmaf(gA.x, c0.x, bA.x), 0.f);
                acc1 += fmaxf(fmaf(gA.y, c0.y, bA.y), 0.f);
                acc2 += fmaxf(fmaf(gB.x, c1.x, bB.x), 0.f);
                acc3 += fmaxf(fmaf(gB.y, c1.y, bB.y), 0.f);
            }
            if (j < cnt) {
                int s0 = __shfl_sync(0xffffffffu, sidx, j);
                uint2 mu0 = __ldg(reinterpret_cast<const uint2*>(hWr + (size_t)s0 * 128) + lane);
                float2 a0 = __half22float2(*reinterpret_cast<const __half2*>(&mu0.x));
                float2 a1 = __half22float2(*reinterpret_cast<const __half2*>(&mu0.y));
                acc0 += fmaxf(fmaf(gA.x, a0.x, bA.x), 0.f);
                acc1 += fmaxf(fmaf(gA.y, a0.y, bA.y), 0.f);
                acc2 += fmaxf(fmaf(gB.x, a1.x, bB.x), 0.f);
                acc3 += fmaxf(fmaf(gB.y, a1.y, bB.y), 0.f);
            }
        }
    }

    float4* o = reinterpret_cast<float4*>(out + (size_t)d * 128) + lane;
    float4 cur = *o;
    cur.x += acc0; cur.y += acc1; cur.z += acc2; cur.w += acc3;
    *o = cur;
}

// ---------------------------------------------------------------------------
extern "C" void kernel_launch(void* const* d_in, const int* in_sizes, int n_in,
                              void* d_out, int out_size)
{
    const float* feat   = (const float*)d_in[0];
    const int*   src    = (const int*)  d_in[1];
    const int*   dst    = (const int*)  d_in[2];
    const int*   etypes = (const int*)  d_in[3];
    const float* W_rel  = (const float*)d_in[4];
    const float* film   = (const float*)d_in[5];
    const float* bias   = (const float*)d_in[6];
    const float* loopw  = (const float*)d_in[7];
    float* out = (float*)d_out;

    const int N = in_sizes[0] / FD;     // 50000
    const int E = in_sizes[1];          // 800000
    const int nbins = N * NRELS;
    const int nblk1 = (nbins + SCAN_BLK - 1) / SCAN_BLK;   // 196

    cudaFuncSetAttribute(gemm_mma_kernel,
                         cudaFuncAttributeMaxDynamicSharedMemorySize, SMEM_TOT);

    // Edge sort (independent of GEMM)
    zero_cnt<<<(nbins + 1023) / 1024, 1024>>>(nbins);
    hist_kernel<<<(E + 255) / 256, 256>>>(dst, etypes, E);
    scan1_kernel<<<nblk1, SCAN_BLK>>>(nbins);
    scan2_kernel<<<1, 256>>>(nblk1, nbins, E);
    scan3_kernel<<<nblk1, SCAN_BLK>>>(nbins);
    scatter_kernel<<<(E + 255) / 256, 256>>>(src, dst, etypes, E);

    // Dense phase
    prep_weights<<<NTILES * 8, 256>>>(W_rel, film, loopw);
    int mtiles = (N + 127) / 128;
    gemm_mma_kernel<<<mtiles, 256, SMEM_TOT>>>(feat, bias, out, N);

    // Segmented aggregation (needs hW/hF/out + sort)
    edge_seg_kernel<<<(N * 32 + 255) / 256, 256>>>(out, N);
}

// round 12
// speedup vs baseline: 2.4596x; 1.0403x over previous
#include <cuda_runtime.h>
#include <cuda_fp16.h>
#include <stdint.h>

#define MAX_NODES 50000
#define MAX_EDGES 800000
#define FD        128
#define NRELS     4
#define NTILES    13
#define NBINS_MAX (NRELS * MAX_NODES)
#define SCAN_BLK  1024
#define NBLK1     ((NBINS_MAX + SCAN_BLK - 1) / SCAN_BLK)   // 196

// Scratch (fp16): hW[r][n][128], hF[r][n][256] (gamma | beta)
__device__ __half g_hW[NRELS * MAX_NODES * 128];   // 51.2 MB
__device__ __half g_hF[NRELS * MAX_NODES * 256];   // 102.4 MB
// Pre-swizzled fp16 weight tiles: 32KB per tile
__device__ unsigned char g_Bw[NTILES * 32768];     // 416 KB (L2-resident)
// Edge sort by key = dst*4 + etype
__device__ int      g_cnt[NBINS_MAX];
__device__ int      g_off[NBINS_MAX + 1];
__device__ int      g_pos[NBINS_MAX];
__device__ int      g_blksum[256];
__device__ int      g_flag[256];
__device__ uint32_t g_srt[MAX_EDGES];

// ---------------------------------------------------------------------------
// Swizzle map for 128x128 fp16 tile [row][k]: row stride 256B, 16B chunks
// XOR-permuted by row&7 -> conflict-free ldmatrix.
// ---------------------------------------------------------------------------
__host__ __device__ __forceinline__ uint32_t amap(int row, int k2) {
    return (uint32_t)(row * 256 + ((((k2 >> 4) ^ (row & 7)) << 4) | (k2 & 15)));
}

__device__ __forceinline__ uint32_t smem_u32(const void* p) {
    uint32_t a;
    asm("{ .reg .u64 t; cvta.to.shared.u64 t, %1; cvt.u32.u64 %0, t; }"
        : "=r"(a) : "l"(p));
    return a;
}

__device__ __forceinline__ void ldsm_x4(uint32_t* r, uint32_t addr) {
    asm volatile("ldmatrix.sync.aligned.m8n8.x4.shared.b16 {%0,%1,%2,%3}, [%4];"
                 : "=r"(r[0]), "=r"(r[1]), "=r"(r[2]), "=r"(r[3]) : "r"(addr));
}
__device__ __forceinline__ void ldsm_x2(uint32_t* r, uint32_t addr) {
    asm volatile("ldmatrix.sync.aligned.m8n8.x2.shared.b16 {%0,%1}, [%2];"
                 : "=r"(r[0]), "=r"(r[1]) : "r"(addr));
}
__device__ __forceinline__ void mma16816(float* c, const uint32_t* a, const uint32_t* b) {
    asm volatile("mma.sync.aligned.m16n8k16.row.col.f32.f16.f16.f32 "
                 "{%0,%1,%2,%3}, {%4,%5,%6,%7}, {%8,%9}, {%0,%1,%2,%3};"
                 : "+f"(c[0]), "+f"(c[1]), "+f"(c[2]), "+f"(c[3])
                 : "r"(a[0]), "r"(a[1]), "r"(a[2]), "r"(a[3]), "r"(b[0]), "r"(b[1]));
}
#define CP_ASYNC16(dst, src) \
    asm volatile("cp.async.ca.shared.global [%0], [%1], 16;" :: "r"(dst), "l"(src) : "memory")
#define CP_COMMIT() asm volatile("cp.async.commit_group;" ::: "memory")
#define CP_WAIT(n)  asm volatile("cp.async.wait_group %0;" :: "n"(n) : "memory")

__device__ __forceinline__ uint32_t cvt2h(float v0, float v1) {
    __half h0 = __float2half_rn(v0);
    __half h1 = __float2half_rn(v1);
    return (uint32_t)__half_as_ushort(h0) | ((uint32_t)__half_as_ushort(h1) << 16);
}

// ---------------------------------------------------------------------------
// K1: fused zero (counts + flags) and weight prep.
//   blocks [0, NBLK1)          : zero g_cnt (+ block 0 zeros g_flag)
//   blocks [NBLK1, NBLK1 + 26) : prep weights (2 blocks per column tile)
// ---------------------------------------------------------------------------
__global__ __launch_bounds__(1024)
void k1_zero_prep(const float* __restrict__ W_rel,
                  const float* __restrict__ film_rel,
                  const float* __restrict__ loop_w,
                  int nbins)
{
    const int b   = blockIdx.x;
    const int tid = threadIdx.x;

    if (b < NBLK1) {
        int i = b * 1024 + tid;
        if (i < nbins) g_cnt[i] = 0;
        if (b == 0 && tid < 256) g_flag[tid] = 0;
        return;
    }

    // ---- prep: 26 blocks, 2 per tile; each block does 2048 of 4096 li ----
    const int pb  = b - NBLK1;
    const int ct  = pb >> 1;
    const int hsel = pb & 1;

    const float* bptr;
    int strideD;
    if (ct < 4)       { bptr = W_rel + (size_t)ct * FD * 128; strideD = 128; }
    else if (ct < 12) {
        int idx = ct - 4, rel = idx >> 1, half = idx & 1;
        bptr = film_rel + (size_t)rel * FD * 256 + half * 128;
        strideD = 256;
    }
    else              { bptr = loop_w; strideD = 128; }

    unsigned char* dhi = g_Bw + (size_t)ct * 32768;

    #pragma unroll
    for (int s = 0; s < 2; ++s) {
        int li = hsel * 2048 + s * 1024 + tid;   // 0..4095
        int n  = li & 127;
        int d4 = (li >> 7) * 4;
        uint32_t w0 = cvt2h(__ldg(bptr + (size_t)(d4    ) * strideD + n),
                            __ldg(bptr + (size_t)(d4 + 1) * strideD + n));
        uint32_t w1 = cvt2h(__ldg(bptr + (size_t)(d4 + 2) * strideD + n),
                            __ldg(bptr + (size_t)(d4 + 3) * strideD + n));
        *reinterpret_cast<uint2*>(dhi + amap(n, d4 * 2)) = make_uint2(w0, w1);
    }
}

// ---------------------------------------------------------------------------
// K2: histogram. key = dst*4 + etype
// ---------------------------------------------------------------------------
__global__ void hist_kernel(const int* __restrict__ dst, const int* __restrict__ et, int E) {
    int i = blockIdx.x * blockDim.x + threadIdx.x;
    if (i < E) atomicAdd(&g_cnt[dst[i] * NRELS + et[i]], 1);
}

// ---------------------------------------------------------------------------
// K3: single-launch scan with all-resident lookback.
// 196 blocks (all co-resident). Each does a local Hillis-Steele, publishes
// its sum with a flag, then sums its predecessors' totals (parallel polls).
// ---------------------------------------------------------------------------
__global__ __launch_bounds__(SCAN_BLK)
void scan_fused(int nbins, int E) {
    __shared__ int sh[SCAN_BLK];
    const int b = blockIdx.x;
    const int t = threadIdx.x;
    const int i = b * SCAN_BLK + t;

    int v = (i < nbins) ? g_cnt[i] : 0;
    sh[t] = v;
    __syncthreads();
    #pragma unroll
    for (int off = 1; off < SCAN_BLK; off <<= 1) {
        int u = (t >= off) ? sh[t - off] : 0;
        __syncthreads();
        sh[t] += u;
        __syncthreads();
    }
    const int local_excl = sh[t] - v;
    const int total = sh[SCAN_BLK - 1];

    if (t == 0) {
        g_blksum[b] = total;
        __threadfence();
        atomicExch(&g_flag[b], 1);
    }

    // sum predecessors (spin until each is published; <=1 per thread)
    int part = 0;
    for (int j = t; j < b; j += SCAN_BLK) {
        while (atomicAdd(&g_flag[j], 0) == 0) { }
        part += g_blksum[j];
    }
    __syncthreads();          // everyone done reading sh (local values in regs)
    sh[t] = part;
    __syncthreads();
    #pragma unroll
    for (int off = SCAN_BLK / 2; off > 0; off >>= 1) {
        if (t < off) sh[t] += sh[t + off];
        __syncthreads();
    }
    const int prefix = sh[0];

    if (i < nbins) {
        int o = prefix + local_excl;
        g_off[i] = o;
        g_pos[i] = o;
    }
    if (b == 0 && t == 0) g_off[nbins] = E;
}

// ---------------------------------------------------------------------------
// K4: fused GEMM (blocks < gemm_blocks) + scatter (remaining blocks).
// Scatter blocks fill the GEMM's tail wave -> scatter is effectively free.
// ---------------------------------------------------------------------------
#define SO_A  0
#define SO_B  32768
#define SMEM_TOT (32768 + 2 * 32768)

__global__ __launch_bounds__(256, 2)
void gemm_scatter_kernel(const float* __restrict__ feat,
                         const float* __restrict__ h_bias,
                         float* __restrict__ out,
                         int Nn,
                         const int* __restrict__ src,
                         const int* __restrict__ dst,
                         const int* __restrict__ et,
                         int E, int gemm_blocks)
{
    if (blockIdx.x >= gemm_blocks) {
        int i = (blockIdx.x - gemm_blocks) * 256 + threadIdx.x;
        if (i < E) {
            int idx = atomicAdd(&g_pos[dst[i] * NRELS + et[i]], 1);
            g_srt[idx] = (uint32_t)src[i];
        }
        return;
    }

    extern __shared__ unsigned char smem[];
    const uint32_t sb = smem_u32(smem);
    const int tid  = threadIdx.x;
    const int wid  = tid >> 5;
    const int lane = tid & 31;
    const int m_base = blockIdx.x * 128;

    // ---- Convert A tile to fp16 SMEM, swizzled ----
    #pragma unroll
    for (int it = 0; it < 16; ++it) {
        int li = it * 256 + tid;
        int m  = li >> 5;
        int k4 = (li & 31) * 4;
        float4 v = make_float4(0.f, 0.f, 0.f, 0.f);
        int row = m_base + m;
        if (row < Nn)
            v = *reinterpret_cast<const float4*>(feat + (size_t)row * FD + k4);
        *reinterpret_cast<uint2*>(smem + SO_A + amap(m, k4 * 2)) =
            make_uint2(cvt2h(v.x, v.y), cvt2h(v.z, v.w));
    }

    const int wm = (wid & 1) * 64;
    const int wn = (wid >> 1) * 32;
    const int lrow_a = lane & 15;
    const int lkh_a  = lane >> 4;
    const int lrow_b = lane & 7;
    const int lkh_b  = (lane >> 3) & 1;
    const int xr7    = lane & 7;

    uint32_t rowoffA[4], rowoffB[4];
    #pragma unroll
    for (int mt = 0; mt < 4; ++mt) rowoffA[mt] = (uint32_t)((wm + mt * 16 + lrow_a) * 256);
    #pragma unroll
    for (int nt = 0; nt < 4; ++nt) rowoffB[nt] = (uint32_t)((wn + nt * 8 + lrow_b) * 256);

    const uint32_t sA = sb + SO_A;

    {   // prefetch B tile 0
        const unsigned char* bsrc = g_Bw;
        uint32_t bdst = sb + SO_B;
        #pragma unroll
        for (int i = 0; i < 8; ++i) {
            int idx = i * 256 + tid;
            CP_ASYNC16(bdst + idx * 16, bsrc + (size_t)idx * 16);
        }
        CP_COMMIT();
    }

    for (int ct = 0; ct < NTILES; ++ct) {
        if (ct + 1 < NTILES) {
            const unsigned char* bsrc = g_Bw + (size_t)(ct + 1) * 32768;
            uint32_t bdst = sb + SO_B + ((ct + 1) & 1) * 32768;
            #pragma unroll
            for (int i = 0; i < 8; ++i) {
                int idx = i * 256 + tid;
                CP_ASYNC16(bdst + idx * 16, bsrc + (size_t)idx * 16);
            }
            CP_COMMIT();
            CP_WAIT(1);
        } else {
            CP_WAIT(0);
        }
        __syncthreads();

        const uint32_t sB = sb + SO_B + (ct & 1) * 32768;

        float acc[4][4][4];
        #pragma unroll
        for (int mt = 0; mt < 4; ++mt)
            #pragma unroll
            for (int nt = 0; nt < 4; ++nt)
                #pragma unroll
                for (int q = 0; q < 4; ++q) acc[mt][nt][q] = 0.f;

        #pragma unroll
        for (int ks = 0; ks < 8; ++ks) {
            uint32_t cA = (uint32_t)((((2 * ks + lkh_a) ^ xr7) & 15) << 4);
            uint32_t cB = (uint32_t)((((2 * ks + lkh_b) ^ xr7) & 15) << 4);
            uint32_t a[4][4];
            #pragma unroll
            for (int mt = 0; mt < 4; ++mt) ldsm_x4(a[mt], sA + rowoffA[mt] + cA);
            uint32_t bh[4][2];
            #pragma unroll
            for (int nt = 0; nt < 4; ++nt) ldsm_x2(bh[nt], sB + rowoffB[nt] + cB);
            #pragma unroll
            for (int mt = 0; mt < 4; ++mt)
                #pragma unroll
                for (int nt = 0; nt < 4; ++nt)
                    mma16816(acc[mt][nt], a[mt], bh[nt]);
        }

        // ---- Epilogue ----
        if (ct == 12) {
            float2 bias2[4];
            #pragma unroll
            for (int nt = 0; nt < 4; ++nt)
                bias2[nt] = *reinterpret_cast<const float2*>(
                    h_bias + wn + nt * 8 + (lane & 3) * 2);
            #pragma unroll
            for (int mt = 0; mt < 4; ++mt) {
                int r0 = m_base + wm + mt * 16 + (lane >> 2);
                #pragma unroll
                for (int nt = 0; nt < 4; ++nt) {
                    int col = wn + nt * 8 + (lane & 3) * 2;
                    float2 v0 = make_float2(acc[mt][nt][0] + bias2[nt].x,
                                            acc[mt][nt][1] + bias2[nt].y);
                    float2 v1 = make_float2(acc[mt][nt][2] + bias2[nt].x,
                                            acc[mt][nt][3] + bias2[nt].y);
                    if (r0 < Nn)
                        *reinterpret_cast<float2*>(out + (size_t)r0 * 128 + col) = v0;
                    if (r0 + 8 < Nn)
                        *reinterpret_cast<float2*>(out + (size_t)(r0 + 8) * 128 + col) = v1;
                }
            }
        } else {
            __half* obase;
            int so;
            if (ct < 4) { obase = g_hW + (size_t)ct * Nn * 128; so = 128; }
            else {
                int idx = ct - 4, rel = idx >> 1, half = idx & 1;
                obase = g_hF + (size_t)rel * Nn * 256 + half * 128;
                so = 256;
            }
            #pragma unroll
            for (int mt = 0; mt < 4; ++mt) {
                int r0 = m_base + wm + mt * 16 + (lane >> 2);
                #pragma unroll
                for (int nt = 0; nt < 4; ++nt) {
                    int col = wn + nt * 8 + (lane & 3) * 2;
                    if (r0 < Nn)
                        *reinterpret_cast<uint32_t*>(obase + (size_t)r0 * so + col) =
                            cvt2h(acc[mt][nt][0], acc[mt][nt][1]);
                    if (r0 + 8 < Nn)
                        *reinterpret_cast<uint32_t*>(obase + (size_t)(r0 + 8) * so + col) =
                            cvt2h(acc[mt][nt][2], acc[mt][nt][3]);
                }
            }
        }
        __syncthreads();
    }
}

// ---------------------------------------------------------------------------
// K5: segmented edge kernel: one warp per dst node, atomic-free.
// ---------------------------------------------------------------------------
__global__ __launch_bounds__(256)
void edge_seg_kernel(float* __restrict__ out, int N)
{
    int d = (blockIdx.x * blockDim.x + threadIdx.x) >> 5;
    if (d >= N) return;
    int lane = threadIdx.x & 31;

    int seg0 = g_off[d * NRELS];
    int seg4 = g_off[d * NRELS + NRELS];
    if (seg0 == seg4) return;   // isolated node: out already has loop+bias

    float acc0 = 0.f, acc1 = 0.f, acc2 = 0.f, acc3 = 0.f;

    #pragma unroll
    for (int rel = 0; rel < NRELS; ++rel) {
        int b = g_off[d * NRELS + rel];
        int e = g_off[d * NRELS + rel + 1];
        if (b == e) continue;

        const uint2* fRow = reinterpret_cast<const uint2*>(
            g_hF + ((size_t)rel * N + d) * 256);
        uint2 gu = __ldg(fRow + lane);
        uint2 bu = __ldg(fRow + lane + 32);
        float2 gA = __half22float2(*reinterpret_cast<const __half2*>(&gu.x));
        float2 gB = __half22float2(*reinterpret_cast<const __half2*>(&gu.y));
        float2 bA = __half22float2(*reinterpret_cast<const __half2*>(&bu.x));
        float2 bB = __half22float2(*reinterpret_cast<const __half2*>(&bu.y));

        const __half* hWr = g_hW + (size_t)rel * N * 128;

        for (int base = b; base < e; base += 32) {
            int cnt = min(32, e - base);
            int sidx = (lane < cnt) ? (int)__ldg(&g_srt[base + lane]) : 0;

            int j = 0;
            for (; j + 2 <= cnt; j += 2) {
                int s0 = __shfl_sync(0xffffffffu, sidx, j);
                int s1 = __shfl_sync(0xffffffffu, sidx, j + 1);
                uint2 mu0 = __ldg(reinterpret_cast<const uint2*>(hWr + (size_t)s0 * 128) + lane);
                uint2 mu1 = __ldg(reinterpret_cast<const uint2*>(hWr + (size_t)s1 * 128) + lane);
                float2 a0 = __half22float2(*reinterpret_cast<const __half2*>(&mu0.x));
                float2 a1 = __half22float2(*reinterpret_cast<const __half2*>(&mu0.y));
                acc0 += fmaxf(fmaf(gA.x, a0.x, bA.x), 0.f);
                acc1 += fmaxf(fmaf(gA.y, a0.y, bA.y), 0.f);
                acc2 += fmaxf(fmaf(gB.x, a1.x, bB.x), 0.f);
                acc3 += fmaxf(fmaf(gB.y, a1.y, bB.y), 0.f);
                float2 c0 = __half22float2(*reinterpret_cast<const __half2*>(&mu1.x));
                float2 c1 = __half22float2(*reinterpret_cast<const __half2*>(&mu1.y));
                acc0 += fmaxf(fmaf(gA.x, c0.x, bA.x), 0.f);
                acc1 += fmaxf(fmaf(gA.y, c0.y, bA.y), 0.f);
                acc2 += fmaxf(fmaf(gB.x, c1.x, bB.x), 0.f);
                acc3 += fmaxf(fmaf(gB.y, c1.y, bB.y), 0.f);
            }
            if (j < cnt) {
                int s0 = __shfl_sync(0xffffffffu, sidx, j);
                uint2 mu0 = __ldg(reinterpret_cast<const uint2*>(hWr + (size_t)s0 * 128) + lane);
                float2 a0 = __half22float2(*reinterpret_cast<const __half2*>(&mu0.x));
                float2 a1 = __half22float2(*reinterpret_cast<const __half2*>(&mu0.y));
                acc0 += fmaxf(fmaf(gA.x, a0.x, bA.x), 0.f);
                acc1 += fmaxf(fmaf(gA.y, a0.y, bA.y), 0.f);
                acc2 += fmaxf(fmaf(gB.x, a1.x, bB.x), 0.f);
                acc3 += fmaxf(fmaf(gB.y, a1.y, bB.y), 0.f);
            }
        }
    }

    float4* o = reinterpret_cast<float4*>(out + (size_t)d * 128) + lane;
    float4 cur = *o;
    cur.x += acc0; cur.y += acc1; cur.z += acc2; cur.w += acc3;
    *o = cur;
}

// ---------------------------------------------------------------------------
extern "C" void kernel_launch(void* const* d_in, const int* in_sizes, int n_in,
                              void* d_out, int out_size)
{
    const float* feat   = (const float*)d_in[0];
    const int*   src    = (const int*)  d_in[1];
    const int*   dst    = (const int*)  d_in[2];
    const int*   etypes = (const int*)  d_in[3];
    const float* W_rel  = (const float*)d_in[4];
    const float* film   = (const float*)d_in[5];
    const float* bias   = (const float*)d_in[6];
    const float* loopw  = (const float*)d_in[7];
    float* out = (float*)d_out;

    const int N = in_sizes[0] / FD;     // 50000
    const int E = in_sizes[1];          // 800000
    const int nbins = N * NRELS;
    const int nblk1 = (nbins + SCAN_BLK - 1) / SCAN_BLK;   // 196

    cudaFuncSetAttribute(gemm_scatter_kernel,
                         cudaFuncAttributeMaxDynamicSharedMemorySize, SMEM_TOT);

    // K1: zero counts/flags + weight prep (fused, independent block ranges)
    k1_zero_prep<<<nblk1 + 2 * NTILES, 1024>>>(W_rel, film, loopw, nbins);

    // K2: histogram
    hist_kernel<<<(E + 255) / 256, 256>>>(dst, etypes, E);

    // K3: single-launch scan (all-resident lookback)
    scan_fused<<<nblk1, SCAN_BLK>>>(nbins, E);

    // K4: GEMM + scatter fused (scatter fills the GEMM tail wave)
    int mtiles = (N + 127) / 128;                       // 391
    int sblocks = (E + 255) / 256;                      // 3125
    gemm_scatter_kernel<<<mtiles + sblocks, 256, SMEM_TOT>>>(
        feat, bias, out, N, src, dst, etypes, E, mtiles);

    // K5: segmented aggregation
    edge_seg_kernel<<<(N * 32 + 255) / 256, 256>>>(out, N);
}